// round 10
// baseline (speedup 1.0000x reference)
#include <cuda_runtime.h>
#include <cuda_bf16.h>
#include <math.h>

#define MT 8192   // B*T rows
#define DD 1024   // in_features
#define NB 8192   // n_bank
#define DO 1024   // out_features

typedef __nv_bfloat16 bf16;

// ---------------- static device scratch (no allocations allowed) -----------
// NOTE: referenced ONLY from device code (host shadow-address trap).
__device__ __align__(128) bf16 g_Qhi[MT * DD];
__device__ __align__(128) bf16 g_Qlo[MT * DD];
__device__ __align__(128) bf16 g_Khi[NB * DD];
__device__ __align__(128) bf16 g_Klo[NB * DD];
__device__ __align__(128) bf16 g_Vthi[DO * NB];        // V^T [DO][NB]
__device__ __align__(128) bf16 g_Vtlo[DO * NB];
__device__ __align__(128) float g_S[(size_t)MT * NB];  // fp32 scores
__device__ __align__(128) bf16 g_Ghi[(size_t)MT * NB]; // gated hi
__device__ __align__(128) bf16 g_Glo[(size_t)MT * NB]; // gated lo
__device__ float g_sumsq[MT];
__device__ float g_scale[MT];

// ---------------- helpers ---------------------------------------------------
__device__ __forceinline__ unsigned smem_u32(const void* p) {
    unsigned a;
    asm("{ .reg .u64 t; cvta.to.shared.u64 t, %1; cvt.u32.u64 %0, t; }"
        : "=r"(a) : "l"(p));
    return a;
}
#define CPA16(d, s) \
    asm volatile("cp.async.cg.shared.global [%0], [%1], 16;" :: "r"(d), "l"(s) : "memory")
#define CPCOMMIT() asm volatile("cp.async.commit_group;" ::: "memory")
#define CPWAIT1()  asm volatile("cp.async.wait_group 1;" ::: "memory")

#define LDSM4(r0, r1, r2, r3, a) \
    asm volatile("ldmatrix.sync.aligned.m8n8.x4.shared.b16 {%0,%1,%2,%3}, [%4];" \
        : "=r"(r0), "=r"(r1), "=r"(r2), "=r"(r3) : "r"(a))
#define LDSM2(r0, r1, a) \
    asm volatile("ldmatrix.sync.aligned.m8n8.x2.shared.b16 {%0,%1}, [%2];" \
        : "=r"(r0), "=r"(r1) : "r"(a))
#define MMA(c, a, b) \
    asm volatile("mma.sync.aligned.m16n8k16.row.col.f32.bf16.bf16.f32 " \
        "{%0,%1,%2,%3},{%4,%5,%6,%7},{%8,%9},{%0,%1,%2,%3};" \
        : "+f"((c)[0]), "+f"((c)[1]), "+f"((c)[2]), "+f"((c)[3]) \
        : "r"((a)[0]), "r"((a)[1]), "r"((a)[2]), "r"((a)[3]), \
          "r"((b)[0]), "r"((b)[1]))

// smem tile: 128 rows x 16 cols bf16, 32B rows, XOR-swizzled 16B segments.
// byte offset of (row, seg) = row*32 + ((seg ^ ((row>>2)&1)) * 16)
#define TILE_B   4096               // 128*32
#define STAGE_B  16384              // Ahi,Alo,Bhi,Blo
// static shared per block: 3 * 16384 = 49152 bytes (48KB limit, no opt-in)

__device__ __forceinline__ unsigned sw_off(int row, int seg) {
    return (unsigned)(row * 32 + ((seg ^ ((row >> 2) & 1)) << 4));
}

__device__ __forceinline__ void load_tile(unsigned sm, const bf16* g, int ld,
                                          int k0, int tid) {
    int row = tid >> 1, seg = tid & 1;
    CPA16(sm + sw_off(row, seg), g + (size_t)row * ld + k0 + seg * 8);
}

// ---------------------------------------------------------------------------
// Fused split-bf16 GEMM: D = (Ahi+Alo)*(Bhi+Blo)^T (lo*lo dropped)
// CTA 128x128, K-chunk 16, 3-stage cp.async pipeline (prefetch distance 2),
// ONE __syncthreads per chunk, 8 warps (2m x 4n), 2 CTAs/SM.
//
// Safety argument for single sync: at iter c the prefetch writes stage
// (c+2)%3 == (c-1)%3. Every warp finished computing chunk c-1 before
// arriving at iter-c's barrier, so after the barrier that buffer is dead.
// wait_group 1 at top of iter c: one commit per iter => the only group
// allowed outstanding is iter c-1's (chunk c+1); chunk c's group (issued
// at iter c-2 / prologue) is complete. The barrier then publishes all
// threads' chunk-c data.
// ---------------------------------------------------------------------------
template<int NC, int LDA, int LDB, bool EPI1>
__global__ __launch_bounds__(256, 2) void gemm_kernel(float* __restrict__ Out,
                                                      int ldo) {
    const bf16* __restrict__ Ahi = EPI1 ? g_Qhi : g_Ghi;
    const bf16* __restrict__ Alo = EPI1 ? g_Qlo : g_Glo;
    const bf16* __restrict__ Bhi = EPI1 ? g_Khi : g_Vthi;
    const bf16* __restrict__ Blo = EPI1 ? g_Klo : g_Vtlo;

    __shared__ __align__(128) char dsm[3 * STAGE_B];   // 49152 bytes
    const unsigned sbase = smem_u32(dsm);
    const int tid = threadIdx.x, lane = tid & 31, wid = tid >> 5;
    const int wm = wid >> 2, wn = wid & 3;
    const int m0 = blockIdx.y * 128, n0 = blockIdx.x * 128;

    const bf16* pAhi = Ahi + (size_t)m0 * LDA;
    const bf16* pAlo = Alo + (size_t)m0 * LDA;
    const bf16* pBhi = Bhi + (size_t)n0 * LDB;
    const bf16* pBlo = Blo + (size_t)n0 * LDB;

    float acc[4][4][4];
#pragma unroll
    for (int f = 0; f < 4; ++f)
#pragma unroll
        for (int g = 0; g < 4; ++g)
#pragma unroll
            for (int j = 0; j < 4; ++j) acc[f][g][j] = 0.f;

    // prologue: stages 0,1 <- chunks 0,1 (one commit each)
#pragma unroll
    for (int s = 0; s < 2; ++s) {
        unsigned sb = sbase + s * STAGE_B;
        int k0 = s * 16;
        load_tile(sb,              pAhi, LDA, k0, tid);
        load_tile(sb + TILE_B,     pAlo, LDA, k0, tid);
        load_tile(sb + 2 * TILE_B, pBhi, LDB, k0, tid);
        load_tile(sb + 3 * TILE_B, pBlo, LDB, k0, tid);
        CPCOMMIT();
    }

    // ldmatrix lane addressing (K=16: one k-step per chunk)
    const int ra = lane & 15, sa = lane >> 4;            // A x4
    const int rb = lane & 7,  sbseg = (lane >> 3) & 1;   // B x2

    int stage = 0;                       // = c % 3
    for (int c = 0; c < NC; ++c) {
        CPWAIT1();                       // own chunk-c loads complete
        __syncthreads();                 // publish chunk c; retire buffer c-1
        // prefetch chunk c+2 into stage (c+2)%3 == (c-1)%3 (dead buffer)
        if (c + 2 < NC) {
            int sn = stage + 2; if (sn >= 3) sn -= 3;
            unsigned sp = sbase + sn * STAGE_B;
            int k0 = (c + 2) * 16;
            load_tile(sp,              pAhi, LDA, k0, tid);
            load_tile(sp + TILE_B,     pAlo, LDA, k0, tid);
            load_tile(sp + 2 * TILE_B, pBhi, LDB, k0, tid);
            load_tile(sp + 3 * TILE_B, pBlo, LDB, k0, tid);
        }
        CPCOMMIT();                      // one commit per iter (may be empty)

        unsigned sb = sbase + stage * STAGE_B;
        unsigned ah[4][4], al[4][4], bh[4][2], bl[4][2];
#pragma unroll
        for (int f = 0; f < 4; ++f) {
            unsigned ad = sb + sw_off(wm * 64 + f * 16 + ra, sa);
            LDSM4(ah[f][0], ah[f][1], ah[f][2], ah[f][3], ad);
            LDSM4(al[f][0], al[f][1], al[f][2], al[f][3], ad + TILE_B);
        }
#pragma unroll
        for (int g = 0; g < 4; ++g) {
            unsigned bd = sb + 2 * TILE_B + sw_off(wn * 32 + g * 8 + rb, sbseg);
            LDSM2(bh[g][0], bh[g][1], bd);
            LDSM2(bl[g][0], bl[g][1], bd + TILE_B);
        }
#pragma unroll
        for (int f = 0; f < 4; ++f)
#pragma unroll
            for (int g = 0; g < 4; ++g) {
                MMA(acc[f][g], ah[f], bh[g]);
                MMA(acc[f][g], al[f], bh[g]);
                MMA(acc[f][g], ah[f], bl[g]);
            }
        if (++stage == 3) stage = 0;
    }

    // epilogue
    const int mrb = m0 + wm * 64 + (lane >> 2);
    const int ncb = n0 + wn * 32 + (lane & 3) * 2;
#pragma unroll
    for (int f = 0; f < 4; ++f) {
        const int r0 = mrb + f * 16;
        float s0 = 0.f, s1 = 0.f;
#pragma unroll
        for (int g = 0; g < 4; ++g) {
            const int cc = ncb + g * 8;
            if (EPI1) {
                *(float2*)&g_S[(size_t)r0 * NB + cc] =
                    make_float2(acc[f][g][0], acc[f][g][1]);
                *(float2*)&g_S[(size_t)(r0 + 8) * NB + cc] =
                    make_float2(acc[f][g][2], acc[f][g][3]);
                s0 += acc[f][g][0] * acc[f][g][0] + acc[f][g][1] * acc[f][g][1];
                s1 += acc[f][g][2] * acc[f][g][2] + acc[f][g][3] * acc[f][g][3];
            } else {
                *(float2*)&Out[(size_t)r0 * ldo + cc] =
                    make_float2(acc[f][g][0], acc[f][g][1]);
                *(float2*)&Out[(size_t)(r0 + 8) * ldo + cc] =
                    make_float2(acc[f][g][2], acc[f][g][3]);
            }
        }
        if (EPI1) {
            s0 += __shfl_xor_sync(0xffffffff, s0, 1);
            s0 += __shfl_xor_sync(0xffffffff, s0, 2);
            s1 += __shfl_xor_sync(0xffffffff, s1, 1);
            s1 += __shfl_xor_sync(0xffffffff, s1, 2);
            if ((lane & 3) == 0) {
                atomicAdd(&g_sumsq[r0], s0);
                atomicAdd(&g_sumsq[r0 + 8], s1);
            }
        }
    }
}

// ---------------- elementwise kernels --------------------------------------
__device__ __forceinline__ void split4(const float4 v, uint2& H, uint2& L) {
    union { unsigned short s[4]; uint2 u; } h, l;
    const float f[4] = {v.x, v.y, v.z, v.w};
#pragma unroll
    for (int j = 0; j < 4; ++j) {
        bf16 hb = __float2bfloat16(f[j]);
        h.s[j] = __bfloat16_as_ushort(hb);
        l.s[j] = __bfloat16_as_ushort(__float2bfloat16(f[j] - __bfloat162float(hb)));
    }
    H = h.u; L = l.u;
}

__global__ __launch_bounds__(256) void splitQK_kernel(const float* __restrict__ q,
                                                      const float* __restrict__ k) {
    size_t i = (size_t)blockIdx.x * 256 + threadIdx.x;    // over MT*DD/4
    uint2 H, L;
    split4(((const float4*)q)[i], H, L);
    ((uint2*)g_Qhi)[i] = H; ((uint2*)g_Qlo)[i] = L;
    split4(((const float4*)k)[i], H, L);
    ((uint2*)g_Khi)[i] = H; ((uint2*)g_Klo)[i] = L;
}

__global__ void vtrans_kernel(const float* __restrict__ V) {
    __shared__ float t[32][33];
    const int o0 = blockIdx.x * 32, n0 = blockIdx.y * 32;
    const int tx = threadIdx.x, ty = threadIdx.y;
    for (int r = ty; r < 32; r += 8)
        t[r][tx] = V[(size_t)(n0 + r) * DO + o0 + tx];
    __syncthreads();
    for (int r = ty; r < 32; r += 8) {
        float f = t[tx][r];
        size_t idx = (size_t)(o0 + r) * NB + n0 + tx;
        bf16 h = __float2bfloat16(f);
        g_Vthi[idx] = h;
        g_Vtlo[idx] = __float2bfloat16(f - __bfloat162float(h));
    }
}

__global__ void zero_sumsq_kernel() {
    int i = blockIdx.x * 256 + threadIdx.x;
    if (i < MT) g_sumsq[i] = 0.f;
}
__global__ void row_scale_kernel2() {
    int i = blockIdx.x * 256 + threadIdx.x;
    if (i < MT) g_scale[i] = 90.50966799187809f / sqrtf(g_sumsq[i]);
}

__global__ __launch_bounds__(256) void gating_kernel() {
    size_t i = (size_t)blockIdx.x * 256 + threadIdx.x;    // over MT*NB/8
    size_t off = i * 8;
    const float sc = g_scale[off >> 13];
    float4 v0 = *(const float4*)(g_S + off);
    float4 v1 = *(const float4*)(g_S + off + 4);
    float f[8] = {v0.x, v0.y, v0.z, v0.w, v1.x, v1.y, v1.z, v1.w};
    union { unsigned short s[8]; uint4 v; } OH, OL;
#pragma unroll
    for (int j = 0; j < 8; ++j) {
        float x = f[j] * sc;
        float g = 0.5f * x * (1.0f + erff(x * 0.70710678118654752f));
        bf16 h = __float2bfloat16(g);
        OH.s[j] = __bfloat16_as_ushort(h);
        OL.s[j] = __bfloat16_as_ushort(__float2bfloat16(g - __bfloat162float(h)));
    }
    *(uint4*)(g_Ghi + off) = OH.v;
    *(uint4*)(g_Glo + off) = OL.v;
}

// ---------------------------------------------------------------------------
extern "C" void kernel_launch(void* const* d_in, const int* in_sizes, int n_in,
                              void* d_out, int out_size) {
    const float* q = (const float*)d_in[0];
    const float* k = (const float*)d_in[1];
    const float* v = (const float*)d_in[2];
    float* o = (float*)d_out;

    splitQK_kernel<<<(MT * DD / 4) / 256, 256>>>(q, k);
    vtrans_kernel<<<dim3(DO / 32, NB / 32), dim3(32, 8)>>>(v);
    zero_sumsq_kernel<<<MT / 256, 256>>>();
    gemm_kernel<DD / 16, DD, DD, true><<<dim3(NB / 128, MT / 128), 256>>>(
        nullptr, NB);
    row_scale_kernel2<<<MT / 256, 256>>>();
    gating_kernel<<<(int)((size_t)MT * NB / 8 / 256), 256>>>();
    gemm_kernel<NB / 16, NB, NB, false><<<dim3(DO / 128, MT / 128), 256>>>(
        o, DO);
}

// round 12
// speedup vs baseline: 1.6351x; 1.6351x over previous
#include <cuda_runtime.h>
#include <cuda_bf16.h>
#include <math.h>

#define MT 8192   // B*T rows
#define DD 1024   // in_features
#define NB 8192   // n_bank
#define DO 1024   // out_features

typedef __nv_bfloat16 bf16;

// ---------------- static device scratch (no allocations allowed) -----------
// NOTE: referenced ONLY from device code (host shadow-address trap).
__device__ __align__(128) bf16 g_Qhi[MT * DD];
__device__ __align__(128) bf16 g_Qlo[MT * DD];
__device__ __align__(128) bf16 g_Khi[NB * DD];
__device__ __align__(128) bf16 g_Klo[NB * DD];
__device__ __align__(128) bf16 g_Vthi[DO * NB];        // V^T [DO][NB]
__device__ __align__(128) bf16 g_Vtlo[DO * NB];
__device__ __align__(128) float g_S[(size_t)MT * NB];  // fp32 scores
__device__ __align__(128) bf16 g_Ghi[(size_t)MT * NB]; // gated hi
__device__ __align__(128) bf16 g_Glo[(size_t)MT * NB]; // gated lo
__device__ float g_sumsq[MT];
__device__ float g_scale[MT];

// ---------------- helpers ---------------------------------------------------
__device__ __forceinline__ unsigned smem_u32(const void* p) {
    unsigned a;
    asm("{ .reg .u64 t; cvta.to.shared.u64 t, %1; cvt.u32.u64 %0, t; }"
        : "=r"(a) : "l"(p));
    return a;
}
#define CPA16(d, s) \
    asm volatile("cp.async.cg.shared.global [%0], [%1], 16;" :: "r"(d), "l"(s) : "memory")
#define CPCOMMIT() asm volatile("cp.async.commit_group;" ::: "memory")
#define CPWAIT1()  asm volatile("cp.async.wait_group 1;" ::: "memory")

#define LDSM4(r0, r1, r2, r3, a) \
    asm volatile("ldmatrix.sync.aligned.m8n8.x4.shared.b16 {%0,%1,%2,%3}, [%4];" \
        : "=r"(r0), "=r"(r1), "=r"(r2), "=r"(r3) : "r"(a))
#define LDSM2(r0, r1, a) \
    asm volatile("ldmatrix.sync.aligned.m8n8.x2.shared.b16 {%0,%1}, [%2];" \
        : "=r"(r0), "=r"(r1) : "r"(a))
#define MMA(c, a, b) \
    asm volatile("mma.sync.aligned.m16n8k16.row.col.f32.bf16.bf16.f32 " \
        "{%0,%1,%2,%3},{%4,%5,%6,%7},{%8,%9},{%0,%1,%2,%3};" \
        : "+f"((c)[0]), "+f"((c)[1]), "+f"((c)[2]), "+f"((c)[3]) \
        : "r"((a)[0]), "r"((a)[1]), "r"((a)[2]), "r"((a)[3]), \
          "r"((b)[0]), "r"((b)[1]))

// smem tile: 128 rows x 16 cols bf16, 32B rows, XOR-swizzled 16B segments.
// byte offset of (row, seg) = row*32 + ((seg ^ ((row>>2)&1)) * 16)
#define TILE_B   4096               // 128*32
#define STAGE_B  16384              // Ahi,Alo,Bhi,Blo
// static shared per block: 2 * 16384 = 32768 bytes -> 2 CTAs/SM

__device__ __forceinline__ unsigned sw_off(int row, int seg) {
    return (unsigned)(row * 32 + ((seg ^ ((row >> 2) & 1)) << 4));
}

__device__ __forceinline__ void load_tile(unsigned sm, const bf16* g, int ld,
                                          int k0, int tid) {
    int row = tid >> 1, seg = tid & 1;
    CPA16(sm + sw_off(row, seg), g + (size_t)row * ld + k0 + seg * 8);
}

// ---------------------------------------------------------------------------
// Fused split-bf16 GEMM: D = (Ahi+Alo)*(Bhi+Blo)^T (lo*lo dropped)
// CTA 128x128, K-chunk 16, 2-stage cp.async double buffer, 8 warps (2m x 4n),
// 2 CTAs/SM. (Round-8 mainloop, verbatim — proven fastest.)
// EPI1: write fp32 g_S + row sumsq atomics.
// else: split-K over blockIdx.z, fp32 atomicAdd into Out.
// ---------------------------------------------------------------------------
template<int NC, int LDA, int LDB, bool EPI1>
__global__ __launch_bounds__(256, 2) void gemm_kernel(float* __restrict__ Out,
                                                      int ldo) {
    const bf16* __restrict__ Ahi = EPI1 ? g_Qhi : g_Ghi;
    const bf16* __restrict__ Alo = EPI1 ? g_Qlo : g_Glo;
    const bf16* __restrict__ Bhi = EPI1 ? g_Khi : g_Vthi;
    const bf16* __restrict__ Blo = EPI1 ? g_Klo : g_Vtlo;

    __shared__ __align__(128) char dsm[2 * STAGE_B];   // 32768 bytes
    const unsigned sbase = smem_u32(dsm);
    const int tid = threadIdx.x, lane = tid & 31, wid = tid >> 5;
    const int wm = wid >> 2, wn = wid & 3;
    const int m0 = blockIdx.y * 128, n0 = blockIdx.x * 128;
    const int kbase = EPI1 ? 0 : (int)blockIdx.z * NC * 16;   // split-K offset

    const bf16* pAhi = Ahi + (size_t)m0 * LDA + kbase;
    const bf16* pAlo = Alo + (size_t)m0 * LDA + kbase;
    const bf16* pBhi = Bhi + (size_t)n0 * LDB + kbase;
    const bf16* pBlo = Blo + (size_t)n0 * LDB + kbase;

    float acc[4][4][4];
#pragma unroll
    for (int f = 0; f < 4; ++f)
#pragma unroll
        for (int g = 0; g < 4; ++g)
#pragma unroll
            for (int j = 0; j < 4; ++j) acc[f][g][j] = 0.f;

    // prologue: stages 0,1 <- chunks 0,1
#pragma unroll
    for (int s = 0; s < 2; ++s) {
        unsigned sb = sbase + s * STAGE_B;
        int k0 = s * 16;
        load_tile(sb,              pAhi, LDA, k0, tid);
        load_tile(sb + TILE_B,     pAlo, LDA, k0, tid);
        load_tile(sb + 2 * TILE_B, pBhi, LDB, k0, tid);
        load_tile(sb + 3 * TILE_B, pBlo, LDB, k0, tid);
        CPCOMMIT();
    }

    // ldmatrix lane addressing (K=16: one k-step per chunk)
    const int ra = lane & 15, sa = lane >> 4;            // A x4
    const int rb = lane & 7,  sbseg = (lane >> 3) & 1;   // B x2

    for (int c = 0; c < NC; ++c) {
        CPWAIT1();
        __syncthreads();
        unsigned sb = sbase + (c & 1) * STAGE_B;
        unsigned ah[4][4], al[4][4], bh[4][2], bl[4][2];
#pragma unroll
        for (int f = 0; f < 4; ++f) {
            unsigned ad = sb + sw_off(wm * 64 + f * 16 + ra, sa);
            LDSM4(ah[f][0], ah[f][1], ah[f][2], ah[f][3], ad);
            LDSM4(al[f][0], al[f][1], al[f][2], al[f][3], ad + TILE_B);
        }
#pragma unroll
        for (int g = 0; g < 4; ++g) {
            unsigned bd = sb + 2 * TILE_B + sw_off(wn * 32 + g * 8 + rb, sbseg);
            LDSM2(bh[g][0], bh[g][1], bd);
            LDSM2(bl[g][0], bl[g][1], bd + TILE_B);
        }
#pragma unroll
        for (int f = 0; f < 4; ++f)
#pragma unroll
            for (int g = 0; g < 4; ++g) {
                MMA(acc[f][g], ah[f], bh[g]);
                MMA(acc[f][g], al[f], bh[g]);
                MMA(acc[f][g], ah[f], bl[g]);
            }
        __syncthreads();
        if (c + 2 < NC) {
            unsigned sn = sbase + (c & 1) * STAGE_B;
            int k0 = (c + 2) * 16;
            load_tile(sn,              pAhi, LDA, k0, tid);
            load_tile(sn + TILE_B,     pAlo, LDA, k0, tid);
            load_tile(sn + 2 * TILE_B, pBhi, LDB, k0, tid);
            load_tile(sn + 3 * TILE_B, pBlo, LDB, k0, tid);
        }
        CPCOMMIT();
    }

    // epilogue
    const int mrb = m0 + wm * 64 + (lane >> 2);
    const int ncb = n0 + wn * 32 + (lane & 3) * 2;
#pragma unroll
    for (int f = 0; f < 4; ++f) {
        const int r0 = mrb + f * 16;
        float s0 = 0.f, s1 = 0.f;
#pragma unroll
        for (int g = 0; g < 4; ++g) {
            const int cc = ncb + g * 8;
            if (EPI1) {
                *(float2*)&g_S[(size_t)r0 * NB + cc] =
                    make_float2(acc[f][g][0], acc[f][g][1]);
                *(float2*)&g_S[(size_t)(r0 + 8) * NB + cc] =
                    make_float2(acc[f][g][2], acc[f][g][3]);
                s0 += acc[f][g][0] * acc[f][g][0] + acc[f][g][1] * acc[f][g][1];
                s1 += acc[f][g][2] * acc[f][g][2] + acc[f][g][3] * acc[f][g][3];
            } else {
                float* p0 = &Out[(size_t)r0 * ldo + cc];
                float* p1 = &Out[(size_t)(r0 + 8) * ldo + cc];
                atomicAdd(p0,     acc[f][g][0]);
                atomicAdd(p0 + 1, acc[f][g][1]);
                atomicAdd(p1,     acc[f][g][2]);
                atomicAdd(p1 + 1, acc[f][g][3]);
            }
        }
        if (EPI1) {
            s0 += __shfl_xor_sync(0xffffffff, s0, 1);
            s0 += __shfl_xor_sync(0xffffffff, s0, 2);
            s1 += __shfl_xor_sync(0xffffffff, s1, 1);
            s1 += __shfl_xor_sync(0xffffffff, s1, 2);
            if ((lane & 3) == 0) {
                atomicAdd(&g_sumsq[r0], s0);
                atomicAdd(&g_sumsq[r0 + 8], s1);
            }
        }
    }
}

// ---------------- elementwise kernels --------------------------------------
__device__ __forceinline__ void split4(const float4 v, uint2& H, uint2& L) {
    union { unsigned short s[4]; uint2 u; } h, l;
    const float f[4] = {v.x, v.y, v.z, v.w};
#pragma unroll
    for (int j = 0; j < 4; ++j) {
        bf16 hb = __float2bfloat16(f[j]);
        h.s[j] = __bfloat16_as_ushort(hb);
        l.s[j] = __bfloat16_as_ushort(__float2bfloat16(f[j] - __bfloat162float(hb)));
    }
    H = h.u; L = l.u;
}

__global__ __launch_bounds__(256) void splitQK_kernel(const float* __restrict__ q,
                                                      const float* __restrict__ k) {
    size_t i = (size_t)blockIdx.x * 256 + threadIdx.x;    // over MT*DD/4
    uint2 H, L;
    split4(((const float4*)q)[i], H, L);
    ((uint2*)g_Qhi)[i] = H; ((uint2*)g_Qlo)[i] = L;
    split4(((const float4*)k)[i], H, L);
    ((uint2*)g_Khi)[i] = H; ((uint2*)g_Klo)[i] = L;
}

__global__ void vtrans_kernel(const float* __restrict__ V) {
    __shared__ float t[32][33];
    const int o0 = blockIdx.x * 32, n0 = blockIdx.y * 32;
    const int tx = threadIdx.x, ty = threadIdx.y;
    for (int r = ty; r < 32; r += 8)
        t[r][tx] = V[(size_t)(n0 + r) * DO + o0 + tx];
    __syncthreads();
    for (int r = ty; r < 32; r += 8) {
        float f = t[tx][r];
        size_t idx = (size_t)(o0 + r) * NB + n0 + tx;
        bf16 h = __float2bfloat16(f);
        g_Vthi[idx] = h;
        g_Vtlo[idx] = __float2bfloat16(f - __bfloat162float(h));
    }
}

__global__ void zero_sumsq_kernel() {
    int i = blockIdx.x * 256 + threadIdx.x;
    if (i < MT) g_sumsq[i] = 0.f;
}
__global__ void row_scale_kernel2() {
    int i = blockIdx.x * 256 + threadIdx.x;
    if (i < MT) g_scale[i] = 90.50966799187809f / sqrtf(g_sumsq[i]);
}

__global__ __launch_bounds__(256) void zero_out_kernel(float* __restrict__ O) {
    size_t i = (size_t)blockIdx.x * 256 + threadIdx.x;    // over MT*DO/4
    ((float4*)O)[i] = make_float4(0.f, 0.f, 0.f, 0.f);
}

__global__ __launch_bounds__(256) void gating_kernel() {
    size_t i = (size_t)blockIdx.x * 256 + threadIdx.x;    // over MT*NB/8
    size_t off = i * 8;
    const float sc = g_scale[off >> 13];
    float4 v0 = *(const float4*)(g_S + off);
    float4 v1 = *(const float4*)(g_S + off + 4);
    float f[8] = {v0.x, v0.y, v0.z, v0.w, v1.x, v1.y, v1.z, v1.w};
    union { unsigned short s[8]; uint4 v; } OH, OL;
#pragma unroll
    for (int j = 0; j < 8; ++j) {
        float x = f[j] * sc;
        float g = 0.5f * x * (1.0f + erff(x * 0.70710678118654752f));
        bf16 h = __float2bfloat16(g);
        OH.s[j] = __bfloat16_as_ushort(h);
        OL.s[j] = __bfloat16_as_ushort(__float2bfloat16(g - __bfloat162float(h)));
    }
    *(uint4*)(g_Ghi + off) = OH.v;
    *(uint4*)(g_Glo + off) = OL.v;
}

// ---------------------------------------------------------------------------
extern "C" void kernel_launch(void* const* d_in, const int* in_sizes, int n_in,
                              void* d_out, int out_size) {
    const float* q = (const float*)d_in[0];
    const float* k = (const float*)d_in[1];
    const float* v = (const float*)d_in[2];
    float* o = (float*)d_out;

    splitQK_kernel<<<(MT * DD / 4) / 256, 256>>>(q, k);
    vtrans_kernel<<<dim3(DO / 32, NB / 32), dim3(32, 8)>>>(v);
    zero_sumsq_kernel<<<MT / 256, 256>>>();
    gemm_kernel<DD / 16, DD, DD, true><<<dim3(NB / 128, MT / 128), 256>>>(
        nullptr, NB);
    row_scale_kernel2<<<MT / 256, 256>>>();
    gating_kernel<<<(int)((size_t)MT * NB / 8 / 256), 256>>>();
    zero_out_kernel<<<(MT * DO / 4) / 256, 256>>>(o);
    // split-K=2: each z-slice sums half the K range into o via atomicAdd
    gemm_kernel<NB / 32, NB, NB, false><<<dim3(DO / 128, MT / 128, 2), 256>>>(
        o, DO);
}

// round 13
// speedup vs baseline: 4.3073x; 2.6343x over previous
#include <cuda_runtime.h>
#include <cuda_fp16.h>
#include <math.h>

#define MT 8192   // B*T rows
#define DD 1024   // in_features
#define NB 8192   // n_bank
#define DO 1024   // out_features

// ---------------- static device scratch (no allocations allowed) -----------
// NOTE: referenced ONLY from device code (host shadow-address trap).
__device__ __align__(128) __half g_Qh[MT * DD];
__device__ __align__(128) __half g_Kh[NB * DD];
__device__ __align__(128) __half g_Vt[DO * NB];        // V^T [DO][NB] fp16
__device__ __align__(128) float  g_S[(size_t)MT * NB]; // fp32 scores
__device__ __align__(128) __half g_G[(size_t)MT * NB]; // gated fp16
__device__ float g_sumsq[MT];
__device__ float g_scale[MT];

// ---------------- helpers ---------------------------------------------------
__device__ __forceinline__ unsigned smem_u32(const void* p) {
    unsigned a;
    asm("{ .reg .u64 t; cvta.to.shared.u64 t, %1; cvt.u32.u64 %0, t; }"
        : "=r"(a) : "l"(p));
    return a;
}
#define CPA16(d, s) \
    asm volatile("cp.async.cg.shared.global [%0], [%1], 16;" :: "r"(d), "l"(s) : "memory")
#define CPCOMMIT() asm volatile("cp.async.commit_group;" ::: "memory")
#define CPWAIT1()  asm volatile("cp.async.wait_group 1;" ::: "memory")

#define LDSM4(r0, r1, r2, r3, a) \
    asm volatile("ldmatrix.sync.aligned.m8n8.x4.shared.b16 {%0,%1,%2,%3}, [%4];" \
        : "=r"(r0), "=r"(r1), "=r"(r2), "=r"(r3) : "r"(a))
#define LDSM2(r0, r1, a) \
    asm volatile("ldmatrix.sync.aligned.m8n8.x2.shared.b16 {%0,%1}, [%2];" \
        : "=r"(r0), "=r"(r1) : "r"(a))
#define MMA(c, a, b) \
    asm volatile("mma.sync.aligned.m16n8k16.row.col.f32.f16.f16.f32 " \
        "{%0,%1,%2,%3},{%4,%5,%6,%7},{%8,%9},{%0,%1,%2,%3};" \
        : "+f"((c)[0]), "+f"((c)[1]), "+f"((c)[2]), "+f"((c)[3]) \
        : "r"((a)[0]), "r"((a)[1]), "r"((a)[2]), "r"((a)[3]), \
          "r"((b)[0]), "r"((b)[1]))

// smem tile: 128 rows x 32 cols fp16, 64B rows = 4 x 16B segments.
// swizzled seg: x = seg ^ ((row>>1)&3)  -> byte off = row*64 + x*16.
// For any ldmatrix 8-lane phase group (8 consecutive rows, same seg), the
// (row parity, x) pairs are 8 distinct offsets mod 128 -> conflict-free.
#define TILE_B   8192               // 128*64
#define STAGE_B  16384              // A,B
// static shared per block: 2 * 16384 = 32768 bytes -> 2 CTAs/SM

__device__ __forceinline__ unsigned sw_off(int row, int seg) {
    return (unsigned)(row * 64 + ((seg ^ ((row >> 1) & 3)) << 4));
}

// tile = 128 rows x 4 segs = 512 x 16B; 256 threads -> 2 cp.async each
__device__ __forceinline__ void load_tile(unsigned sm, const __half* g, int ld,
                                          int k0, int tid) {
#pragma unroll
    for (int j = 0; j < 2; ++j) {
        int i = tid + j * 256;
        int row = i >> 2, seg = i & 3;
        CPA16(sm + sw_off(row, seg), g + (size_t)row * ld + k0 + seg * 8);
    }
}

// ---------------------------------------------------------------------------
// Single-term fp16 GEMM: D = A * B^T  (fp16 in, fp32 accumulate)
// CTA 128x128, K-chunk 32, 2-stage cp.async double buffer, 8 warps (2m x 4n),
// 2 CTAs/SM. (Round-8 pipeline structure, proven fastest.)
// EPI1: write fp32 g_S + row sumsq atomics.
// else: split-K over blockIdx.z, fp32 atomicAdd into Out.
// ---------------------------------------------------------------------------
template<int NC, int LDA, int LDB, bool EPI1>
__global__ __launch_bounds__(256, 2) void gemm_kernel(float* __restrict__ Out,
                                                      int ldo) {
    const __half* __restrict__ A = EPI1 ? g_Qh : g_G;
    const __half* __restrict__ B = EPI1 ? g_Kh : g_Vt;

    __shared__ __align__(128) char dsm[2 * STAGE_B];   // 32768 bytes
    const unsigned sbase = smem_u32(dsm);
    const int tid = threadIdx.x, lane = tid & 31, wid = tid >> 5;
    const int wm = wid >> 2, wn = wid & 3;
    const int m0 = blockIdx.y * 128, n0 = blockIdx.x * 128;
    const int kbase = EPI1 ? 0 : (int)blockIdx.z * NC * 32;   // split-K offset

    const __half* pA = A + (size_t)m0 * LDA + kbase;
    const __half* pB = B + (size_t)n0 * LDB + kbase;

    float acc[4][4][4];
#pragma unroll
    for (int f = 0; f < 4; ++f)
#pragma unroll
        for (int g = 0; g < 4; ++g)
#pragma unroll
            for (int j = 0; j < 4; ++j) acc[f][g][j] = 0.f;

    // prologue: stages 0,1 <- chunks 0,1
#pragma unroll
    for (int s = 0; s < 2; ++s) {
        unsigned sb = sbase + s * STAGE_B;
        int k0 = s * 32;
        load_tile(sb,          pA, LDA, k0, tid);
        load_tile(sb + TILE_B, pB, LDB, k0, tid);
        CPCOMMIT();
    }

    // ldmatrix lane addressing
    const int ra = lane & 15, sa = lane >> 4;            // A x4: row, seg-half
    const int rb = lane & 7,  sbg = (lane >> 3) & 1;     // B x2: row, seg-half

    for (int c = 0; c < NC; ++c) {
        CPWAIT1();
        __syncthreads();
        unsigned sb = sbase + (c & 1) * STAGE_B;
#pragma unroll
        for (int h = 0; h < 2; ++h) {                    // two k16 steps
            unsigned a[4][4], b[4][2];
#pragma unroll
            for (int f = 0; f < 4; ++f) {
                unsigned ad = sb + sw_off(wm * 64 + f * 16 + ra, h * 2 + sa);
                LDSM4(a[f][0], a[f][1], a[f][2], a[f][3], ad);
            }
#pragma unroll
            for (int g = 0; g < 4; ++g) {
                unsigned bd = sb + TILE_B +
                              sw_off(wn * 32 + g * 8 + rb, h * 2 + sbg);
                LDSM2(b[g][0], b[g][1], bd);
            }
#pragma unroll
            for (int f = 0; f < 4; ++f)
#pragma unroll
                for (int g = 0; g < 4; ++g)
                    MMA(acc[f][g], a[f], b[g]);
        }
        __syncthreads();
        if (c + 2 < NC) {
            unsigned sn = sbase + (c & 1) * STAGE_B;
            int k0 = (c + 2) * 32;
            load_tile(sn,          pA, LDA, k0, tid);
            load_tile(sn + TILE_B, pB, LDB, k0, tid);
        }
        CPCOMMIT();
    }

    // epilogue
    const int mrb = m0 + wm * 64 + (lane >> 2);
    const int ncb = n0 + wn * 32 + (lane & 3) * 2;
#pragma unroll
    for (int f = 0; f < 4; ++f) {
        const int r0 = mrb + f * 16;
        float s0 = 0.f, s1 = 0.f;
#pragma unroll
        for (int g = 0; g < 4; ++g) {
            const int cc = ncb + g * 8;
            if (EPI1) {
                *(float2*)&g_S[(size_t)r0 * NB + cc] =
                    make_float2(acc[f][g][0], acc[f][g][1]);
                *(float2*)&g_S[(size_t)(r0 + 8) * NB + cc] =
                    make_float2(acc[f][g][2], acc[f][g][3]);
                s0 += acc[f][g][0] * acc[f][g][0] + acc[f][g][1] * acc[f][g][1];
                s1 += acc[f][g][2] * acc[f][g][2] + acc[f][g][3] * acc[f][g][3];
            } else {
                float* p0 = &Out[(size_t)r0 * ldo + cc];
                float* p1 = &Out[(size_t)(r0 + 8) * ldo + cc];
                atomicAdd(p0,     acc[f][g][0]);
                atomicAdd(p0 + 1, acc[f][g][1]);
                atomicAdd(p1,     acc[f][g][2]);
                atomicAdd(p1 + 1, acc[f][g][3]);
            }
        }
        if (EPI1) {
            s0 += __shfl_xor_sync(0xffffffff, s0, 1);
            s0 += __shfl_xor_sync(0xffffffff, s0, 2);
            s1 += __shfl_xor_sync(0xffffffff, s1, 1);
            s1 += __shfl_xor_sync(0xffffffff, s1, 2);
            if ((lane & 3) == 0) {
                atomicAdd(&g_sumsq[r0], s0);
                atomicAdd(&g_sumsq[r0 + 8], s1);
            }
        }
    }
}

// ---------------- elementwise kernels --------------------------------------
__global__ __launch_bounds__(256) void convQK_kernel(const float* __restrict__ q,
                                                     const float* __restrict__ k) {
    size_t i = (size_t)blockIdx.x * 256 + threadIdx.x;    // over MT*DD/4
    float4 vq = ((const float4*)q)[i];
    float4 vk = ((const float4*)k)[i];
    union { __half h[4]; uint2 u; } H;
    H.h[0] = __float2half_rn(vq.x); H.h[1] = __float2half_rn(vq.y);
    H.h[2] = __float2half_rn(vq.z); H.h[3] = __float2half_rn(vq.w);
    ((uint2*)g_Qh)[i] = H.u;
    H.h[0] = __float2half_rn(vk.x); H.h[1] = __float2half_rn(vk.y);
    H.h[2] = __float2half_rn(vk.z); H.h[3] = __float2half_rn(vk.w);
    ((uint2*)g_Kh)[i] = H.u;
}

__global__ void vtrans_kernel(const float* __restrict__ V) {
    __shared__ float t[32][33];
    const int o0 = blockIdx.x * 32, n0 = blockIdx.y * 32;
    const int tx = threadIdx.x, ty = threadIdx.y;
    for (int r = ty; r < 32; r += 8)
        t[r][tx] = V[(size_t)(n0 + r) * DO + o0 + tx];
    __syncthreads();
    for (int r = ty; r < 32; r += 8)
        g_Vt[(size_t)(o0 + r) * NB + n0 + tx] = __float2half_rn(t[tx][r]);
}

__global__ void zero_sumsq_kernel() {
    int i = blockIdx.x * 256 + threadIdx.x;
    if (i < MT) g_sumsq[i] = 0.f;
}
__global__ void row_scale_kernel2() {
    int i = blockIdx.x * 256 + threadIdx.x;
    if (i < MT) g_scale[i] = 90.50966799187809f / sqrtf(g_sumsq[i]);
}

__global__ __launch_bounds__(256) void zero_out_kernel(float* __restrict__ O) {
    size_t i = (size_t)blockIdx.x * 256 + threadIdx.x;    // over MT*DO/4
    ((float4*)O)[i] = make_float4(0.f, 0.f, 0.f, 0.f);
}

__global__ __launch_bounds__(256) void gating_kernel() {
    size_t i = (size_t)blockIdx.x * 256 + threadIdx.x;    // over MT*NB/8
    size_t off = i * 8;
    const float sc = g_scale[off >> 13];
    float4 v0 = *(const float4*)(g_S + off);
    float4 v1 = *(const float4*)(g_S + off + 4);
    float f[8] = {v0.x, v0.y, v0.z, v0.w, v1.x, v1.y, v1.z, v1.w};
    union { __half h[8]; uint4 v; } OH;
#pragma unroll
    for (int j = 0; j < 8; ++j) {
        float x = f[j] * sc;
        OH.h[j] = __float2half_rn(0.5f * x * (1.0f + erff(x * 0.70710678118654752f)));
    }
    *(uint4*)(g_G + off) = OH.v;
}

// ---------------------------------------------------------------------------
extern "C" void kernel_launch(void* const* d_in, const int* in_sizes, int n_in,
                              void* d_out, int out_size) {
    const float* q = (const float*)d_in[0];
    const float* k = (const float*)d_in[1];
    const float* v = (const float*)d_in[2];
    float* o = (float*)d_out;

    convQK_kernel<<<(MT * DD / 4) / 256, 256>>>(q, k);
    vtrans_kernel<<<dim3(DO / 32, NB / 32), dim3(32, 8)>>>(v);
    zero_sumsq_kernel<<<MT / 256, 256>>>();
    gemm_kernel<DD / 32, DD, DD, true><<<dim3(NB / 128, MT / 128), 256>>>(
        nullptr, NB);
    row_scale_kernel2<<<MT / 256, 256>>>();
    gating_kernel<<<(int)((size_t)MT * NB / 8 / 256), 256>>>();
    zero_out_kernel<<<(MT * DO / 4) / 256, 256>>>(o);
    // split-K=2: each z-slice sums half the K range into o via atomicAdd
    gemm_kernel<NB / 64, NB, NB, false><<<dim3(DO / 128, MT / 128, 2), 256>>>(
        o, DO);
}

// round 14
// speedup vs baseline: 4.3259x; 1.0043x over previous
#include <cuda_runtime.h>
#include <cuda_fp16.h>
#include <math.h>

#define MT 8192   // B*T rows
#define DD 1024   // in_features
#define NB 8192   // n_bank
#define DO 1024   // out_features

// ---------------- static device scratch (no allocations allowed) -----------
// NOTE: referenced ONLY from device code (host shadow-address trap).
__device__ __align__(128) __half g_Qh[MT * DD];
__device__ __align__(128) __half g_Kh[NB * DD];
__device__ __align__(128) __half g_Vt[DO * NB];         // V^T [DO][NB] fp16
__device__ __align__(128) __half g_Sh[(size_t)MT * NB]; // fp16 scores
__device__ __align__(128) __half g_G[(size_t)MT * NB];  // gated fp16
__device__ float g_sumsq[MT];
__device__ float g_scale[MT];

// ---------------- helpers ---------------------------------------------------
__device__ __forceinline__ unsigned smem_u32(const void* p) {
    unsigned a;
    asm("{ .reg .u64 t; cvta.to.shared.u64 t, %1; cvt.u32.u64 %0, t; }"
        : "=r"(a) : "l"(p));
    return a;
}
#define CPA16(d, s) \
    asm volatile("cp.async.cg.shared.global [%0], [%1], 16;" :: "r"(d), "l"(s) : "memory")
#define CPCOMMIT() asm volatile("cp.async.commit_group;" ::: "memory")
#define CPWAIT1()  asm volatile("cp.async.wait_group 1;" ::: "memory")

#define LDSM4(r0, r1, r2, r3, a) \
    asm volatile("ldmatrix.sync.aligned.m8n8.x4.shared.b16 {%0,%1,%2,%3}, [%4];" \
        : "=r"(r0), "=r"(r1), "=r"(r2), "=r"(r3) : "r"(a))
#define MMA(c, a, b) \
    asm volatile("mma.sync.aligned.m16n8k16.row.col.f32.f16.f16.f32 " \
        "{%0,%1,%2,%3},{%4,%5,%6,%7},{%8,%9},{%0,%1,%2,%3};" \
        : "+f"((c)[0]), "+f"((c)[1]), "+f"((c)[2]), "+f"((c)[3]) \
        : "r"((a)[0]), "r"((a)[1]), "r"((a)[2]), "r"((a)[3]), \
          "r"((b)[0]), "r"((b)[1]))

// smem tile: 128 rows x 32 cols fp16, 64B rows = 4 x 16B segments.
// swizzled seg: x = seg ^ ((row>>1)&3)  -> byte off = row*64 + x*16.
// Any ldmatrix 8-lane phase group (8 consecutive rows, same seg) hits 8
// distinct 16B offsets mod 128 -> conflict-free.
#define TILE_B   8192               // 128*64
#define STAGE_B  16384              // A,B
// static shared per block: 2 * 16384 = 32768 bytes -> 2 CTAs/SM

__device__ __forceinline__ unsigned sw_off(int row, int seg) {
    return (unsigned)(row * 64 + ((seg ^ ((row >> 1) & 3)) << 4));
}

// tile = 128 rows x 4 segs = 512 x 16B; 256 threads -> 2 cp.async each
__device__ __forceinline__ void load_tile(unsigned sm, const __half* g, int ld,
                                          int k0, int tid) {
#pragma unroll
    for (int j = 0; j < 2; ++j) {
        int i = tid + j * 256;
        int row = i >> 2, seg = i & 3;
        CPA16(sm + sw_off(row, seg), g + (size_t)row * ld + k0 + seg * 8);
    }
}

// ---------------------------------------------------------------------------
// Single-term fp16 GEMM: D = A * B^T (fp16 in, fp32 accumulate)
// CTA 128x128, K-chunk 32, 2-stage cp.async double buffer, 8 warps (2m x 4n),
// 2 CTAs/SM. B fragments via paired LDSM4 (2 n8-tiles per ldmatrix).
// EPI1: write fp16 g_Sh + row sumsq atomics (from fp32 acc).
// else: split-K over blockIdx.z, fp32 atomicAdd into Out.
// ---------------------------------------------------------------------------
template<int NC, int LDA, int LDB, bool EPI1>
__global__ __launch_bounds__(256, 2) void gemm_kernel(float* __restrict__ Out,
                                                      int ldo) {
    const __half* __restrict__ A = EPI1 ? g_Qh : g_G;
    const __half* __restrict__ B = EPI1 ? g_Kh : g_Vt;

    __shared__ __align__(128) char dsm[2 * STAGE_B];   // 32768 bytes
    const unsigned sbase = smem_u32(dsm);
    const int tid = threadIdx.x, lane = tid & 31, wid = tid >> 5;
    const int wm = wid >> 2, wn = wid & 3;
    const int m0 = blockIdx.y * 128, n0 = blockIdx.x * 128;
    const int kbase = EPI1 ? 0 : (int)blockIdx.z * NC * 32;   // split-K offset

    const __half* pA = A + (size_t)m0 * LDA + kbase;
    const __half* pB = B + (size_t)n0 * LDB + kbase;

    float acc[4][4][4];
#pragma unroll
    for (int f = 0; f < 4; ++f)
#pragma unroll
        for (int g = 0; g < 4; ++g)
#pragma unroll
            for (int j = 0; j < 4; ++j) acc[f][g][j] = 0.f;

    // prologue: stages 0,1 <- chunks 0,1
#pragma unroll
    for (int s = 0; s < 2; ++s) {
        unsigned sb = sbase + s * STAGE_B;
        int k0 = s * 32;
        load_tile(sb,          pA, LDA, k0, tid);
        load_tile(sb + TILE_B, pB, LDB, k0, tid);
        CPCOMMIT();
    }

    // ldmatrix lane addressing
    const int ra = lane & 15, sa = lane >> 4;            // A x4: row, seg-half
    // B paired x4: two n8 tiles per ldmatrix
    const int rbp = (lane & 7) + ((lane >> 4) << 3);     // row within 16-row pair
    const int sbp = (lane >> 3) & 1;                     // k-half seg

    for (int c = 0; c < NC; ++c) {
        CPWAIT1();
        __syncthreads();
        unsigned sb = sbase + (c & 1) * STAGE_B;
#pragma unroll
        for (int h = 0; h < 2; ++h) {                    // two k16 steps
            unsigned a[4][4], b[4][2];
#pragma unroll
            for (int f = 0; f < 4; ++f) {
                unsigned ad = sb + sw_off(wm * 64 + f * 16 + ra, h * 2 + sa);
                LDSM4(a[f][0], a[f][1], a[f][2], a[f][3], ad);
            }
#pragma unroll
            for (int p = 0; p < 2; ++p) {                // g-pair {2p, 2p+1}
                unsigned bd = sb + TILE_B +
                              sw_off(wn * 32 + p * 16 + rbp, h * 2 + sbp);
                LDSM4(b[2 * p][0], b[2 * p][1],
                      b[2 * p + 1][0], b[2 * p + 1][1], bd);
            }
#pragma unroll
            for (int f = 0; f < 4; ++f)
#pragma unroll
                for (int g = 0; g < 4; ++g)
                    MMA(acc[f][g], a[f], b[g]);
        }
        __syncthreads();
        if (c + 2 < NC) {
            unsigned sn = sbase + (c & 1) * STAGE_B;
            int k0 = (c + 2) * 32;
            load_tile(sn,          pA, LDA, k0, tid);
            load_tile(sn + TILE_B, pB, LDB, k0, tid);
        }
        CPCOMMIT();
    }

    // epilogue
    const int mrb = m0 + wm * 64 + (lane >> 2);
    const int ncb = n0 + wn * 32 + (lane & 3) * 2;
#pragma unroll
    for (int f = 0; f < 4; ++f) {
        const int r0 = mrb + f * 16;
        float s0 = 0.f, s1 = 0.f;
#pragma unroll
        for (int g = 0; g < 4; ++g) {
            const int cc = ncb + g * 8;
            if (EPI1) {
                *(__half2*)&g_Sh[(size_t)r0 * NB + cc] =
                    __floats2half2_rn(acc[f][g][0], acc[f][g][1]);
                *(__half2*)&g_Sh[(size_t)(r0 + 8) * NB + cc] =
                    __floats2half2_rn(acc[f][g][2], acc[f][g][3]);
                s0 += acc[f][g][0] * acc[f][g][0] + acc[f][g][1] * acc[f][g][1];
                s1 += acc[f][g][2] * acc[f][g][2] + acc[f][g][3] * acc[f][g][3];
            } else {
                float* p0 = &Out[(size_t)r0 * ldo + cc];
                float* p1 = &Out[(size_t)(r0 + 8) * ldo + cc];
                atomicAdd(p0,     acc[f][g][0]);
                atomicAdd(p0 + 1, acc[f][g][1]);
                atomicAdd(p1,     acc[f][g][2]);
                atomicAdd(p1 + 1, acc[f][g][3]);
            }
        }
        if (EPI1) {
            s0 += __shfl_xor_sync(0xffffffff, s0, 1);
            s0 += __shfl_xor_sync(0xffffffff, s0, 2);
            s1 += __shfl_xor_sync(0xffffffff, s1, 1);
            s1 += __shfl_xor_sync(0xffffffff, s1, 2);
            if ((lane & 3) == 0) {
                atomicAdd(&g_sumsq[r0], s0);
                atomicAdd(&g_sumsq[r0 + 8], s1);
            }
        }
    }
}

// ---------------- elementwise kernels --------------------------------------
__global__ __launch_bounds__(256) void convQK_kernel(const float* __restrict__ q,
                                                     const float* __restrict__ k) {
    size_t i = (size_t)blockIdx.x * 256 + threadIdx.x;    // over MT*DD/4
    float4 vq = ((const float4*)q)[i];
    float4 vk = ((const float4*)k)[i];
    union { __half h[4]; uint2 u; } H;
    H.h[0] = __float2half_rn(vq.x); H.h[1] = __float2half_rn(vq.y);
    H.h[2] = __float2half_rn(vq.z); H.h[3] = __float2half_rn(vq.w);
    ((uint2*)g_Qh)[i] = H.u;
    H.h[0] = __float2half_rn(vk.x); H.h[1] = __float2half_rn(vk.y);
    H.h[2] = __float2half_rn(vk.z); H.h[3] = __float2half_rn(vk.w);
    ((uint2*)g_Kh)[i] = H.u;
}

__global__ void vtrans_kernel(const float* __restrict__ V) {
    __shared__ float t[32][33];
    const int o0 = blockIdx.x * 32, n0 = blockIdx.y * 32;
    const int tx = threadIdx.x, ty = threadIdx.y;
    for (int r = ty; r < 32; r += 8)
        t[r][tx] = V[(size_t)(n0 + r) * DO + o0 + tx];
    __syncthreads();
    for (int r = ty; r < 32; r += 8)
        g_Vt[(size_t)(o0 + r) * NB + n0 + tx] = __float2half_rn(t[tx][r]);
}

__global__ void zero_sumsq_kernel() {
    int i = blockIdx.x * 256 + threadIdx.x;
    if (i < MT) g_sumsq[i] = 0.f;
}
__global__ void row_scale_kernel2() {
    int i = blockIdx.x * 256 + threadIdx.x;
    if (i < MT) g_scale[i] = 90.50966799187809f / sqrtf(g_sumsq[i]);
}

__global__ __launch_bounds__(256) void zero_out_kernel(float* __restrict__ O) {
    size_t i = (size_t)blockIdx.x * 256 + threadIdx.x;    // over MT*DO/4
    ((float4*)O)[i] = make_float4(0.f, 0.f, 0.f, 0.f);
}

__global__ __launch_bounds__(256) void gating_kernel() {
    size_t i = (size_t)blockIdx.x * 256 + threadIdx.x;    // over MT*NB/8
    size_t off = i * 8;
    const float sc = g_scale[off >> 13];
    union { __half h[8]; uint4 v; } IN, OH;
    IN.v = *(const uint4*)(g_Sh + off);
#pragma unroll
    for (int j = 0; j < 8; ++j) {
        float x = __half2float(IN.h[j]) * sc;
        OH.h[j] = __float2half_rn(0.5f * x * (1.0f + erff(x * 0.70710678118654752f)));
    }
    *(uint4*)(g_G + off) = OH.v;
}

// ---------------------------------------------------------------------------
extern "C" void kernel_launch(void* const* d_in, const int* in_sizes, int n_in,
                              void* d_out, int out_size) {
    const float* q = (const float*)d_in[0];
    const float* k = (const float*)d_in[1];
    const float* v = (const float*)d_in[2];
    float* o = (float*)d_out;

    convQK_kernel<<<(MT * DD / 4) / 256, 256>>>(q, k);
    vtrans_kernel<<<dim3(DO / 32, NB / 32), dim3(32, 8)>>>(v);
    zero_sumsq_kernel<<<MT / 256, 256>>>();
    gemm_kernel<DD / 32, DD, DD, true><<<dim3(NB / 128, MT / 128), 256>>>(
        nullptr, NB);
    row_scale_kernel2<<<MT / 256, 256>>>();
    gating_kernel<<<(int)((size_t)MT * NB / 8 / 256), 256>>>();
    zero_out_kernel<<<(MT * DO / 4) / 256, 256>>>(o);
    // split-K=4: each z-slice sums a quarter of K into o via atomicAdd
    gemm_kernel<NB / 128, NB, NB, false><<<dim3(DO / 128, MT / 128, 4), 256>>>(
        o, DO);
}